// round 2
// baseline (speedup 1.0000x reference)
#include <cuda_runtime.h>
#include <cuda_bf16.h>
#include <cstdint>

#define NN   100000
#define NE   1600000
#define HID  128
#define ODIM 64

// ---------------- scratch (no allocations allowed; __device__ globals) -----
__device__ int    g_w64;                 // 1 if edge_index is int64, 0 if int32
__device__ int    g_deg[NN];
__device__ int    g_cursor[NN];
__device__ int    g_rowptr[NN + 1];
__device__ int    g_csr[NE];
__device__ float  g_inv[NN];
__device__ float4 g_mean[(size_t)NN * 32];        // NN x 128 floats, 16B aligned
__device__ float4 g_h[3][(size_t)NN * 32];        // 3 x NN x 128 floats

// ---------------- index width autodetect ----------------------------------
__global__ void k_detect(const long long* __restrict__ ei) {
    __shared__ int bad;
    if (threadIdx.x == 0) bad = 0;
    __syncthreads();
    long long v = ei[threadIdx.x];
    long long u = ei[threadIdx.x + 256];
    if (v < 0 || v >= NN || u < 0 || u >= NN) bad = 1;
    __syncthreads();
    if (threadIdx.x == 0) g_w64 = bad ? 0 : 1;
}

__device__ __forceinline__ int load_idx(const void* ei, size_t i, int w64) {
    if (w64) return (int)((const long long*)ei)[i];
    return ((const int*)ei)[i];
}

// ---------------- CSR build ------------------------------------------------
__global__ void k_zero() {
    int i = blockIdx.x * blockDim.x + threadIdx.x;
    if (i < NN) { g_deg[i] = 0; g_cursor[i] = 0; }
}

__global__ void k_count(const void* __restrict__ ei) {
    int e = blockIdx.x * blockDim.x + threadIdx.x;
    if (e < NE) {
        int w64 = g_w64;
        int d = load_idx(ei, (size_t)NE + e, w64);
        if ((unsigned)d < (unsigned)NN) atomicAdd(&g_deg[d], 1);
    }
}

// single-block exclusive scan of g_deg -> g_rowptr, also 1/max(deg,1) -> g_inv
__global__ void k_scan() {
    __shared__ int warpsum[32];
    int tid = threadIdx.x, lane = tid & 31, wp = tid >> 5;
    int carry = 0;
    for (int base = 0; base < NN; base += 1024) {
        int i = base + tid;
        int v = (i < NN) ? g_deg[i] : 0;
        int s = v;
        #pragma unroll
        for (int off = 1; off < 32; off <<= 1) {
            int t = __shfl_up_sync(0xffffffff, s, off);
            if (lane >= off) s += t;
        }
        if (lane == 31) warpsum[wp] = s;
        __syncthreads();
        if (wp == 0) {
            int ws = warpsum[lane];
            #pragma unroll
            for (int off = 1; off < 32; off <<= 1) {
                int t = __shfl_up_sync(0xffffffff, ws, off);
                if (lane >= off) ws += t;
            }
            warpsum[lane] = ws;
        }
        __syncthreads();
        int incl = s + (wp > 0 ? warpsum[wp - 1] : 0);
        if (i < NN) {
            g_rowptr[i] = carry + incl - v;
            g_inv[i] = 1.0f / (float)(v > 1 ? v : 1);
        }
        carry += warpsum[31];
        __syncthreads();
    }
    if (tid == 0) g_rowptr[NN] = carry;
}

__global__ void k_fill(const void* __restrict__ ei) {
    int e = blockIdx.x * blockDim.x + threadIdx.x;
    if (e < NE) {
        int w64 = g_w64;
        int d = load_idx(ei, (size_t)NE + e, w64);
        int s = load_idx(ei, (size_t)e, w64);
        if ((unsigned)d < (unsigned)NN && (unsigned)s < (unsigned)NN) {
            int pos = g_rowptr[d] + atomicAdd(&g_cursor[d], 1);
            if (pos < NE) g_csr[pos] = s;
        }
    }
}

// ---------------- mean aggregation: one warp per node ----------------------
__global__ void k_agg(const float* __restrict__ x0, int layer) {
    const float4* x4 = (layer == 0) ? (const float4*)x0 : g_h[layer - 1];
    int wp = (blockIdx.x * blockDim.x + threadIdx.x) >> 5;
    int lane = threadIdx.x & 31;
    if (wp >= NN) return;
    int s = g_rowptr[wp], e = g_rowptr[wp + 1];
    float4 acc = make_float4(0.f, 0.f, 0.f, 0.f);
    for (int p = s; p < e; ++p) {
        int j = g_csr[p];
        float4 v = x4[(size_t)j * 32 + lane];
        acc.x += v.x; acc.y += v.y; acc.z += v.z; acc.w += v.w;
    }
    float inv = g_inv[wp];
    acc.x *= inv; acc.y *= inv; acc.z *= inv; acc.w *= inv;
    g_mean[(size_t)wp * 32 + lane] = acc;
}

// ---------------- layer GEMM: relu(mean@Wl + x@Wr + b) ---------------------
// block: 256 threads, tile 128 nodes x 128 cols; thread: 16 rows x 4 cols
__global__ void __launch_bounds__(256) k_layer(
        const float* __restrict__ x0, int layer,
        const float* __restrict__ Wl, const float* __restrict__ Wr,
        const float* __restrict__ bias) {
    const float* xin  = (layer == 0) ? x0 : (const float*)g_h[layer - 1];
    const float* mean = (const float*)g_mean;
    float* out = (float*)g_h[layer];

    __shared__ __align__(16) float sm [16][132];
    __shared__ __align__(16) float sx [16][132];
    __shared__ __align__(16) float swl[16][128];
    __shared__ __align__(16) float swr[16][128];

    int tid = threadIdx.x;
    int m0  = blockIdx.x * 128;
    int tx  = tid & 31;   // cols tx*4 .. tx*4+3
    int ty  = tid >> 5;   // rows ty*16 .. ty*16+15

    float acc[16][4];
    #pragma unroll
    for (int i = 0; i < 16; i++) { acc[i][0]=0.f; acc[i][1]=0.f; acc[i][2]=0.f; acc[i][3]=0.f; }

    for (int kb = 0; kb < 128; kb += 16) {
        // A tiles (mean, x): 128 rows x 16 cols, stored transposed [k][m]
        #pragma unroll
        for (int t = tid; t < 512; t += 256) {
            int r = t >> 2, c4 = (t & 3) * 4;
            int row = m0 + r;
            float4 vm = make_float4(0.f,0.f,0.f,0.f), vx = vm;
            if (row < NN) {
                vm = *(const float4*)&mean[(size_t)row * 128 + kb + c4];
                vx = *(const float4*)&xin [(size_t)row * 128 + kb + c4];
            }
            sm[c4+0][r]=vm.x; sm[c4+1][r]=vm.y; sm[c4+2][r]=vm.z; sm[c4+3][r]=vm.w;
            sx[c4+0][r]=vx.x; sx[c4+1][r]=vx.y; sx[c4+2][r]=vx.z; sx[c4+3][r]=vx.w;
        }
        // weight tiles: [16 k][128 j], direct layout
        #pragma unroll
        for (int t = tid; t < 512; t += 256) {
            int r = t >> 5, c = (t & 31) * 4;
            *(float4*)&swl[r][c] = *(const float4*)&Wl[(kb + r) * 128 + c];
            *(float4*)&swr[r][c] = *(const float4*)&Wr[(kb + r) * 128 + c];
        }
        __syncthreads();

        #pragma unroll 4
        for (int k = 0; k < 16; ++k) {
            float4 wl  = *(const float4*)&swl[k][tx * 4];
            float4 wr4 = *(const float4*)&swr[k][tx * 4];
            #pragma unroll
            for (int i4 = 0; i4 < 4; ++i4) {
                float4 mv = *(const float4*)&sm[k][ty * 16 + i4 * 4];
                float4 xv = *(const float4*)&sx[k][ty * 16 + i4 * 4];
                float mq[4] = {mv.x, mv.y, mv.z, mv.w};
                float xq[4] = {xv.x, xv.y, xv.z, xv.w};
                #pragma unroll
                for (int q = 0; q < 4; ++q) {
                    int i = i4 * 4 + q;
                    acc[i][0] = fmaf(mq[q], wl.x, acc[i][0]);
                    acc[i][0] = fmaf(xq[q], wr4.x, acc[i][0]);
                    acc[i][1] = fmaf(mq[q], wl.y, acc[i][1]);
                    acc[i][1] = fmaf(xq[q], wr4.y, acc[i][1]);
                    acc[i][2] = fmaf(mq[q], wl.z, acc[i][2]);
                    acc[i][2] = fmaf(xq[q], wr4.z, acc[i][2]);
                    acc[i][3] = fmaf(mq[q], wl.w, acc[i][3]);
                    acc[i][3] = fmaf(xq[q], wr4.w, acc[i][3]);
                }
            }
        }
        __syncthreads();
    }

    float4 bb = *(const float4*)&bias[tx * 4];
    #pragma unroll
    for (int i = 0; i < 16; ++i) {
        int row = m0 + ty * 16 + i;
        if (row < NN) {
            float4 o;
            o.x = fmaxf(acc[i][0] + bb.x, 0.f);
            o.y = fmaxf(acc[i][1] + bb.y, 0.f);
            o.z = fmaxf(acc[i][2] + bb.z, 0.f);
            o.w = fmaxf(acc[i][3] + bb.w, 0.f);
            *(float4*)&out[(size_t)row * 128 + tx * 4] = o;
        }
    }
}

// ---------------- final JK-cat GEMM: [N,384] @ [384,64] + fc_b -------------
// block: 256 threads, tile 128 nodes x 64 cols; thread: 8 rows x 4 cols
__global__ void __launch_bounds__(256) k_final(
        const float* __restrict__ fw, const float* __restrict__ fb,
        float* __restrict__ out) {
    __shared__ __align__(16) float sh[16][132];
    __shared__ __align__(16) float sw[16][64];

    int tid = threadIdx.x;
    int m0  = blockIdx.x * 128;
    int tx  = tid & 15;   // cols tx*4
    int ty  = tid >> 4;   // rows ty*8 .. ty*8+7

    float acc[8][4];
    #pragma unroll
    for (int i = 0; i < 8; i++) { acc[i][0]=0.f; acc[i][1]=0.f; acc[i][2]=0.f; acc[i][3]=0.f; }

    for (int kb = 0; kb < 384; kb += 16) {
        const float* hsrc = (const float*)g_h[kb >> 7];
        int kk = kb & 127;
        #pragma unroll
        for (int t = tid; t < 512; t += 256) {
            int r = t >> 2, c4 = (t & 3) * 4;
            int row = m0 + r;
            float4 v = make_float4(0.f,0.f,0.f,0.f);
            if (row < NN) v = *(const float4*)&hsrc[(size_t)row * 128 + kk + c4];
            sh[c4+0][r]=v.x; sh[c4+1][r]=v.y; sh[c4+2][r]=v.z; sh[c4+3][r]=v.w;
        }
        {
            int r = tid >> 4, c = (tid & 15) * 4;
            *(float4*)&sw[r][c] = *(const float4*)&fw[(kb + r) * 64 + c];
        }
        __syncthreads();

        #pragma unroll 8
        for (int k = 0; k < 16; ++k) {
            float4 w4 = *(const float4*)&sw[k][tx * 4];
            #pragma unroll
            for (int i4 = 0; i4 < 2; ++i4) {
                float4 hv = *(const float4*)&sh[k][ty * 8 + i4 * 4];
                float hq[4] = {hv.x, hv.y, hv.z, hv.w};
                #pragma unroll
                for (int q = 0; q < 4; ++q) {
                    int i = i4 * 4 + q;
                    acc[i][0] = fmaf(hq[q], w4.x, acc[i][0]);
                    acc[i][1] = fmaf(hq[q], w4.y, acc[i][1]);
                    acc[i][2] = fmaf(hq[q], w4.z, acc[i][2]);
                    acc[i][3] = fmaf(hq[q], w4.w, acc[i][3]);
                }
            }
        }
        __syncthreads();
    }

    float4 bb = *(const float4*)&fb[tx * 4];
    #pragma unroll
    for (int i = 0; i < 8; ++i) {
        int row = m0 + ty * 8 + i;
        if (row < NN) {
            float4 o;
            o.x = acc[i][0] + bb.x;
            o.y = acc[i][1] + bb.y;
            o.z = acc[i][2] + bb.z;
            o.w = acc[i][3] + bb.w;
            *(float4*)&out[(size_t)row * 64 + tx * 4] = o;
        }
    }
}

// ---------------- launch ----------------------------------------------------
extern "C" void kernel_launch(void* const* d_in, const int* in_sizes, int n_in,
                              void* d_out, int out_size) {
    const float* x  = (const float*)d_in[0];
    const void*  ei = d_in[1];
    const float* Wl = (const float*)d_in[2];
    const float* Wr = (const float*)d_in[3];
    const float* b  = (const float*)d_in[4];
    const float* fw = (const float*)d_in[5];
    const float* fb = (const float*)d_in[6];
    float* out = (float*)d_out;

    k_detect<<<1, 256>>>((const long long*)ei);
    k_zero  <<<(NN + 255) / 256, 256>>>();
    k_count <<<(NE + 255) / 256, 256>>>(ei);
    k_scan  <<<1, 1024>>>();
    k_fill  <<<(NE + 255) / 256, 256>>>(ei);

    const int agg_blocks  = (NN + 7) / 8;          // warp per node, 8 warps/block
    const int gemm_blocks = (NN + 127) / 128;

    for (int l = 0; l < 3; ++l) {
        k_agg  <<<agg_blocks, 256>>>(x, l);
        k_layer<<<gemm_blocks, 256>>>(x, l,
                                      Wl + (size_t)l * 128 * 128,
                                      Wr + (size_t)l * 128 * 128,
                                      b  + (size_t)l * 128);
    }
    k_final<<<gemm_blocks, 256>>>(fw, fb, out);
}